// round 10
// baseline (speedup 1.0000x reference)
#include <cuda_runtime.h>
#include <cuda_bf16.h>
#include <cstdint>

// VQVAE nearest-codebook: single-pass bf16 mma.sync fast scores, inline
// provisional-threshold pushes, warp-parallel exact fp32 rescore.
// z:[131072,64] f32, cb:[512,64] f32. out = (gather, gather).

#define Dm 64
#define Kc 512
#define ROWS_CTA 512
#define THREADS 512
#define MARGIN 2e-3f
#define QCAP 256

__device__ float g_ee[Kc];            // exact sequential ||e_j||^2
__device__ int g_eemax_i = 0;         // max ee (float bits)
__device__ unsigned g_cbw[Kc * 32];   // codebook rows, bf16x2 words, B-pair permuted

// ---- smem layout (bytes) ----
#define SM_ZBW  0                      // 512 x 36 u32 bf16x2(-2z)                73728
#define SM_BSW  73728                  // 512 x 40 u32 codebook (pitch 40)        81920
#define SM_ZZS  155648                 // 512 f32 exact zz                         2048
#define SM_MINR 157696                 // 512 u64 (score_bits<<32 | j)             4096
#define SM_QCNT 161792                 // 16 i32 (+pad)                             128
#define SM_QUE  161920                 // 16 x 256 u32 candidates                 16384
#define SM_TOTAL 178304

__global__ void prep_kernel(const float* __restrict__ cb) {
    int j = blockIdx.x * blockDim.x + threadIdx.x;
    if (j < Kc) {
        const float* e = cb + j * Dm;
        float s = 0.0f;
#pragma unroll
        for (int k = 0; k < Dm; ++k) s = __fadd_rn(s, __fmul_rn(e[k], e[k]));
        g_ee[j] = s;
        atomicMax(&g_eemax_i, __float_as_int(s));   // s >= 0: int order == float order
        // permuted: position p holds word w = (p&~7) + ((p>>1)&3) + 4*(p&1)
#pragma unroll
        for (int p = 0; p < 32; ++p) {
            int w = (p & ~7) + ((p >> 1) & 3) + 4 * (p & 1);
            __nv_bfloat162 b = __float22bfloat162_rn(make_float2(e[2 * w], e[2 * w + 1]));
            g_cbw[j * 32 + p] = *(unsigned*)&b;
        }
    }
}

__device__ __forceinline__ void mma16816(float& c0, float& c1, float& c2, float& c3,
                                         unsigned a0, unsigned a1, unsigned a2, unsigned a3,
                                         unsigned b0, unsigned b1) {
    asm volatile("mma.sync.aligned.m16n8k16.row.col.f32.bf16.bf16.f32 "
                 "{%0,%1,%2,%3},{%4,%5,%6,%7},{%8,%9},{%0,%1,%2,%3};"
                 : "+f"(c0), "+f"(c1), "+f"(c2), "+f"(c3)
                 : "r"(a0), "r"(a1), "r"(a2), "r"(a3), "r"(b0), "r"(b1));
}

// Score one 8-code tile for this warp's 32 rows (M=32): c0..c3 rows ra/ra+8,
// c4..c7 rows ra+16/ra+24.
__device__ __forceinline__ void score_tile(const unsigned* __restrict__ bsw,
                                           const unsigned* a, int t, int rg, int q,
                                           float& c0, float& c1, float& c2, float& c3,
                                           float& c4, float& c5, float& c6, float& c7) {
    const unsigned* bp = bsw + (t * 8 + rg) * 40 + 2 * q;
    uint2 b0 = *(const uint2*)(bp);
    uint2 b1 = *(const uint2*)(bp + 8);
    uint2 b2 = *(const uint2*)(bp + 16);
    uint2 b3 = *(const uint2*)(bp + 24);
    c0 = c1 = c2 = c3 = c4 = c5 = c6 = c7 = 0.f;
    mma16816(c0, c1, c2, c3, a[0], a[1], a[2], a[3], b0.x, b0.y);
    mma16816(c0, c1, c2, c3, a[4], a[5], a[6], a[7], b1.x, b1.y);
    mma16816(c0, c1, c2, c3, a[8], a[9], a[10], a[11], b2.x, b2.y);
    mma16816(c0, c1, c2, c3, a[12], a[13], a[14], a[15], b3.x, b3.y);
    mma16816(c4, c5, c6, c7, a[16], a[17], a[18], a[19], b0.x, b0.y);
    mma16816(c4, c5, c6, c7, a[20], a[21], a[22], a[23], b1.x, b1.y);
    mma16816(c4, c5, c6, c7, a[24], a[25], a[26], a[27], b2.x, b2.y);
    mma16816(c4, c5, c6, c7, a[28], a[29], a[30], a[31], b3.x, b3.y);
}

// Exact rescore (sequential fp32, reference rounding) + 64-bit atomicMin commit.
// key=(score_bits<<32)|j: scores >= 0 so bit order == value order; ties -> min j.
__device__ __noinline__ void exact_commit(unsigned pk, const float* __restrict__ z,
                                          const float* __restrict__ cb, size_t blockRow,
                                          const float* zzs, unsigned long long* minr) {
    int row = pk & 511;
    int j = pk >> 9;
    const float4* zp = (const float4*)(z + (blockRow + row) * Dm);
    const float4* ep = (const float4*)(cb + (size_t)j * Dm);
    float dot = 0.0f;
#pragma unroll
    for (int i = 0; i < 16; ++i) {
        float4 a = __ldg(zp + i);
        float4 b = __ldg(ep + i);
        dot = __fmaf_rn(a.x, b.x, dot);
        dot = __fmaf_rn(a.y, b.y, dot);
        dot = __fmaf_rn(a.z, b.z, dot);
        dot = __fmaf_rn(a.w, b.w, dot);
    }
    float sx = __fadd_rn(__fadd_rn(zzs[row], g_ee[j]), __fmul_rn(-2.0f, dot));
    unsigned long long key = ((unsigned long long)__float_as_uint(sx) << 32) | (unsigned)j;
    atomicMin(minr + row, key);
}

__global__ void __launch_bounds__(THREADS, 1)
vq_kernel(const float* __restrict__ z, const float* __restrict__ cb,
          float* __restrict__ out, long long half) {
    extern __shared__ char sm[];
    unsigned* zbw = (unsigned*)(sm + SM_ZBW);
    unsigned* bsw = (unsigned*)(sm + SM_BSW);
    float* zzs = (float*)(sm + SM_ZZS);
    unsigned long long* minr = (unsigned long long*)(sm + SM_MINR);
    int* qcnt = (int*)(sm + SM_QCNT);
    unsigned* que = (unsigned*)(sm + SM_QUE);

    const int tid = threadIdx.x, lane = tid & 31, wid = tid >> 5;
    const int q = lane & 3, rg = lane >> 2;
    const size_t blockRow = (size_t)blockIdx.x * ROWS_CTA;

    if (tid < 16) qcnt[tid] = 0;
    minr[tid] = ~0ull;

    // ---------------- prolog: z rows + exact zz + bf16(-2z) ----------------
    {
        const float4* zr = (const float4*)(z + (blockRow + tid) * Dm);
        float4 v[16];
#pragma unroll
        for (int i = 0; i < 16; ++i) v[i] = zr[i];
        float zz = 0.0f;
#pragma unroll
        for (int i = 0; i < 16; ++i) {
            zz = __fadd_rn(zz, __fmul_rn(v[i].x, v[i].x));
            zz = __fadd_rn(zz, __fmul_rn(v[i].y, v[i].y));
            zz = __fadd_rn(zz, __fmul_rn(v[i].z, v[i].z));
            zz = __fadd_rn(zz, __fmul_rn(v[i].w, v[i].w));
        }
        zzs[tid] = zz;
        unsigned p[32];
#pragma unroll
        for (int i = 0; i < 16; ++i) {
            __nv_bfloat162 b0 = __float22bfloat162_rn(make_float2(-2.f * v[i].x, -2.f * v[i].y));
            __nv_bfloat162 b1 = __float22bfloat162_rn(make_float2(-2.f * v[i].z, -2.f * v[i].w));
            p[2 * i] = *(unsigned*)&b0;
            p[2 * i + 1] = *(unsigned*)&b1;
        }
        uint4* d4 = (uint4*)(zbw + tid * 36);
#pragma unroll
        for (int i = 0; i < 8; ++i) d4[i] = make_uint4(p[4 * i], p[4 * i + 1], p[4 * i + 2], p[4 * i + 3]);
    }
    // codebook bf16x2 words -> pitch-40 smem (vectorized, coalesced)
    {
        const uint4* src = (const uint4*)g_cbw;
#pragma unroll
        for (int it = 0; it < 8; ++it) {
            int u = tid + it * THREADS;          // 0..4095 uint4 chunks
            int r = u >> 3, c4 = u & 7;
            *(uint4*)(bsw + r * 40 + c4 * 4) = src[u];
        }
    }
    __syncthreads();

    // ---------------- A fragments: M=32 (rows ra, ra+8, ra+16, ra+24) ----------------
    const int ra = wid * 32 + rg;
    unsigned a[32];
#pragma unroll
    for (int b = 0; b < 2; ++b)
#pragma unroll
        for (int ks = 0; ks < 4; ++ks) {
            int rbase = (ra + 16 * b) * 36;
            a[b * 16 + ks * 4 + 0] = zbw[rbase + q + ks * 8];
            a[b * 16 + ks * 4 + 1] = zbw[rbase + 8 * 36 + q + ks * 8];
            a[b * 16 + ks * 4 + 2] = zbw[rbase + q + 4 + ks * 8];
            a[b * 16 + ks * 4 + 3] = zbw[rbase + 8 * 36 + q + 4 + ks * 8];
        }

    const float marginFast = MARGIN + __int_as_float(g_eemax_i);

    // ---------------- bootstrap thresholds from tile 0 (no pushes) ----------------
    float m0, m1, m2, m3;
    {
        float c0, c1, c2, c3, c4, c5, c6, c7;
        score_tile(bsw, a, 0, rg, q, c0, c1, c2, c3, c4, c5, c6, c7);
        m0 = fminf(c0, c1); m1 = fminf(c2, c3);
        m2 = fminf(c4, c5); m3 = fminf(c6, c7);
    }
    float r0 = m0, r1 = m1, r2 = m2, r3 = m3;
#pragma unroll
    for (int off = 1; off < 4; off <<= 1) {
        r0 = fminf(r0, __shfl_xor_sync(0xffffffffu, r0, off));
        r1 = fminf(r1, __shfl_xor_sync(0xffffffffu, r1, off));
        r2 = fminf(r2, __shfl_xor_sync(0xffffffffu, r2, off));
        r3 = fminf(r3, __shfl_xor_sync(0xffffffffu, r3, off));
    }
    float t0 = r0 + marginFast, t1 = r1 + marginFast;
    float t2 = r2 + marginFast, t3 = r3 + marginFast;
    float thrmax = fmaxf(fmaxf(t0, t1), fmaxf(t2, t3));

    // ---------------- single pass: score each tile, push inline ----------------
#define PUSH(rowv, jv) do {                                                       \
        unsigned pk_ = (unsigned)(rowv) | ((unsigned)(jv) << 9);                  \
        int qi_ = atomicAdd(qcnt + wid, 1);                                       \
        if (qi_ < QCAP) que[wid * QCAP + qi_] = pk_;                              \
        else exact_commit(pk_, z, cb, blockRow, zzs, minr);                       \
    } while (0)

#pragma unroll 1
    for (int ch = 0; ch < 16; ++ch) {
#pragma unroll
        for (int tt = 0; tt < 4; ++tt) {
            int t = ch * 4 + tt;
            float c0, c1, c2, c3, c4, c5, c6, c7;
            score_tile(bsw, a, t, rg, q, c0, c1, c2, c3, c4, c5, c6, c7);
            m0 = fminf(m0, fminf(c0, c1));
            m1 = fminf(m1, fminf(c2, c3));
            m2 = fminf(m2, fminf(c4, c5));
            m3 = fminf(m3, fminf(c6, c7));
            float tmin = fminf(fminf(fminf(c0, c1), fminf(c2, c3)),
                               fminf(fminf(c4, c5), fminf(c6, c7)));
            if (tmin <= thrmax) {          // rare: only tiles holding a candidate
                int jb = t * 8 + 2 * q;
                if (c0 <= t0) PUSH(ra, jb);
                if (c1 <= t0) PUSH(ra, jb + 1);
                if (c2 <= t1) PUSH(ra + 8, jb);
                if (c3 <= t1) PUSH(ra + 8, jb + 1);
                if (c4 <= t2) PUSH(ra + 16, jb);
                if (c5 <= t2) PUSH(ra + 16, jb + 1);
                if (c6 <= t3) PUSH(ra + 24, jb);
                if (c7 <= t3) PUSH(ra + 24, jb + 1);
            }
        }
        // refresh provisional thresholds (monotone non-increasing)
        r0 = m0; r1 = m1; r2 = m2; r3 = m3;
#pragma unroll
        for (int off = 1; off < 4; off <<= 1) {
            r0 = fminf(r0, __shfl_xor_sync(0xffffffffu, r0, off));
            r1 = fminf(r1, __shfl_xor_sync(0xffffffffu, r1, off));
            r2 = fminf(r2, __shfl_xor_sync(0xffffffffu, r2, off));
            r3 = fminf(r3, __shfl_xor_sync(0xffffffffu, r3, off));
        }
        t0 = r0 + marginFast; t1 = r1 + marginFast;
        t2 = r2 + marginFast; t3 = r3 + marginFast;
        thrmax = fmaxf(fmaxf(t0, t1), fmaxf(t2, t3));
    }
#undef PUSH

    // ---------------- drain: 32 lanes rescore distinct candidates ----------------
    __syncwarp();
    int n = *(volatile int*)(qcnt + wid);
    if (n > QCAP) n = QCAP;
    for (int base = 0; base < n; base += 32) {
        int k2 = base + lane;
        if (k2 < n) exact_commit(que[wid * QCAP + k2], z, cb, blockRow, zzs, minr);
    }
    __syncthreads();

    // ---------------- gather + write both tuple halves ----------------
    {
        int j = (int)(unsigned)(minr[tid] & 0xFFFFFFFFull);
        size_t g = blockRow + tid;
        const float4* s4 = (const float4*)(cb + (size_t)j * Dm);
        float4* o1 = (float4*)(out + g * Dm);
        float4* o2 = (half > 0) ? (float4*)(out + half + g * Dm) : nullptr;
#pragma unroll
        for (int i = 0; i < 16; ++i) {
            float4 tv = s4[i];
            o1[i] = tv;
            if (o2) o2[i] = tv;
        }
    }
}

extern "C" void kernel_launch(void* const* d_in, const int* in_sizes, int n_in,
                              void* d_out, int out_size) {
    const float* z = (const float*)d_in[0];
    const float* cb = (const float*)d_in[1];
    float* out = (float*)d_out;
    const int N = in_sizes[0] / Dm;                      // 131072
    long long half = ((long long)out_size >= 2LL * N * Dm) ? (long long)out_size / 2 : 0;

    cudaFuncSetAttribute(vq_kernel, cudaFuncAttributeMaxDynamicSharedMemorySize, SM_TOTAL);
    prep_kernel<<<2, 256>>>(cb);
    vq_kernel<<<N / ROWS_CTA, THREADS, SM_TOTAL>>>(z, cb, out, half);
}

// round 11
// speedup vs baseline: 1.9344x; 1.9344x over previous
#include <cuda_runtime.h>
#include <cuda_bf16.h>
#include <cuda_fp16.h>
#include <cstdint>

// VQVAE nearest-codebook: bf16 mma.sync fast scores + warp-parallel exact fp32
// rescore. Single fused kernel (prep folded in).
// z:[131072,64] f32, cb:[512,64] f32. out = (gather, gather).

#define Dm 64
#define Kc 512
#define ROWS_CTA 512
#define THREADS 512
#define NTILES 64
#define MARGIN 2e-3f
#define PRUNE_SLACK 5e-4f
#define QCAP 256

// ---- smem layout (bytes) ----
#define SM_ZBW  0                      // 512 x 36 u32 bf16x2(-2z), pitch 36      73728
#define SM_BSW  73728                  // 512 x 40 u32 codebook pairs (pitch 40)  81920
#define SM_TMIN 155648                 // 16 warps x 64 tiles x 8 rg, fp16        16384
#define SM_EEF  172032                 // 512 f32 exact ee                         2048
#define SM_ZZS  174080                 // 512 f32 exact zz                         2048
#define SM_MINR 176128                 // 512 u64 (score_bits<<32 | j)             4096
#define SM_QCNT 180224                 // 16 i32 (+pad)                             128
#define SM_QUE  180352                 // 16 x 256 u32 candidates                 16384
#define SM_TOTAL 196736

__device__ __forceinline__ void mma16816(float& c0, float& c1, float& c2, float& c3,
                                         unsigned a0, unsigned a1, unsigned a2, unsigned a3,
                                         unsigned b0, unsigned b1) {
    asm volatile("mma.sync.aligned.m16n8k16.row.col.f32.bf16.bf16.f32 "
                 "{%0,%1,%2,%3},{%4,%5,%6,%7},{%8,%9},{%0,%1,%2,%3};"
                 : "+f"(c0), "+f"(c1), "+f"(c2), "+f"(c3)
                 : "r"(a0), "r"(a1), "r"(a2), "r"(a3), "r"(b0), "r"(b1));
}

// Exact rescore (sequential fp32, matches reference rounding) + 64-bit atomicMin
// commit. key=(score_bits<<32)|j: scores >= 0 so bit order == value order;
// ties resolve to smallest j (first-index, as jnp.argmin).
__device__ __noinline__ void exact_commit(unsigned pk, const float* __restrict__ z,
                                          const float* __restrict__ cb, size_t blockRow,
                                          const float* zzs, const float* eef,
                                          unsigned long long* minr) {
    int row = pk & 511;
    int j = pk >> 9;
    const float4* zp = (const float4*)(z + (blockRow + row) * Dm);
    const float4* ep = (const float4*)(cb + (size_t)j * Dm);
    float dot = 0.0f;
#pragma unroll
    for (int i = 0; i < 16; ++i) {
        float4 a = __ldg(zp + i);
        float4 b = __ldg(ep + i);
        dot = __fmaf_rn(a.x, b.x, dot);
        dot = __fmaf_rn(a.y, b.y, dot);
        dot = __fmaf_rn(a.z, b.z, dot);
        dot = __fmaf_rn(a.w, b.w, dot);
    }
    float sx = __fadd_rn(__fadd_rn(zzs[row], eef[j]), __fmul_rn(-2.0f, dot));
    unsigned long long key = ((unsigned long long)__float_as_uint(sx) << 32) | (unsigned)j;
    atomicMin(minr + row, key);
}

__global__ void __launch_bounds__(THREADS, 1)
vq_kernel(const float* __restrict__ z, const float* __restrict__ cb,
          float* __restrict__ out, long long half) {
    extern __shared__ char sm[];
    unsigned* zbw = (unsigned*)(sm + SM_ZBW);
    unsigned* bsw = (unsigned*)(sm + SM_BSW);
    __half* tminp = (__half*)(sm + SM_TMIN);
    float* eef = (float*)(sm + SM_EEF);
    float* zzs = (float*)(sm + SM_ZZS);
    unsigned long long* minr = (unsigned long long*)(sm + SM_MINR);
    int* qcnt = (int*)(sm + SM_QCNT);
    unsigned* que = (unsigned*)(sm + SM_QUE);

    const int tid = threadIdx.x, lane = tid & 31, wid = tid >> 5;
    const int q = lane & 3, rg = lane >> 2;
    const size_t blockRow = (size_t)blockIdx.x * ROWS_CTA;

    if (tid < 16) qcnt[tid] = 0;
    minr[tid] = ~0ull;

    // ---------------- prolog A: z row -> exact zz + bf16(-2z), pitch 36 ----------------
    {
        const float4* zr = (const float4*)(z + (blockRow + tid) * Dm);
        float4 v[16];
#pragma unroll
        for (int i = 0; i < 16; ++i) v[i] = zr[i];
        float zz = 0.0f;
#pragma unroll
        for (int i = 0; i < 16; ++i) {
            zz = __fadd_rn(zz, __fmul_rn(v[i].x, v[i].x));
            zz = __fadd_rn(zz, __fmul_rn(v[i].y, v[i].y));
            zz = __fadd_rn(zz, __fmul_rn(v[i].z, v[i].z));
            zz = __fadd_rn(zz, __fmul_rn(v[i].w, v[i].w));
        }
        zzs[tid] = zz;
        unsigned p[32];
#pragma unroll
        for (int i = 0; i < 16; ++i) {
            __nv_bfloat162 b0 = __float22bfloat162_rn(make_float2(-2.f * v[i].x, -2.f * v[i].y));
            __nv_bfloat162 b1 = __float22bfloat162_rn(make_float2(-2.f * v[i].z, -2.f * v[i].w));
            p[2 * i] = *(unsigned*)&b0;
            p[2 * i + 1] = *(unsigned*)&b1;
        }
        uint4* d4 = (uint4*)(zbw + tid * 36);
#pragma unroll
        for (int i = 0; i < 8; ++i) d4[i] = make_uint4(p[4 * i], p[4 * i + 1], p[4 * i + 2], p[4 * i + 3]);
    }

    // ---------------- prolog B: codebook row tid -> exact ee + bf16 pairs ----------------
    // Pair permutation (verified): position p holds original bf16x2 word
    // w = (p&~7) + ((p>>1)&3) + 4*(p&1), so an mma's (b0,b1) pair sits adjacent
    // (one LDS.64 per k-step).
    {
        const float4* er = (const float4*)(cb + (size_t)tid * Dm);
        float4 ev[16];
#pragma unroll
        for (int i = 0; i < 16; ++i) ev[i] = er[i];
        float s = 0.0f;
#pragma unroll
        for (int i = 0; i < 16; ++i) {
            s = __fadd_rn(s, __fmul_rn(ev[i].x, ev[i].x));
            s = __fadd_rn(s, __fmul_rn(ev[i].y, ev[i].y));
            s = __fadd_rn(s, __fmul_rn(ev[i].z, ev[i].z));
            s = __fadd_rn(s, __fmul_rn(ev[i].w, ev[i].w));
        }
        eef[tid] = s;
        unsigned pw[32];
#pragma unroll
        for (int p = 0; p < 32; ++p) {
            int w = (p & ~7) + ((p >> 1) & 3) + 4 * (p & 1);
            float4 f = ev[w >> 1];
            float lo = (w & 1) ? f.z : f.x;
            float hi = (w & 1) ? f.w : f.y;
            __nv_bfloat162 b = __float22bfloat162_rn(make_float2(lo, hi));
            pw[p] = *(unsigned*)&b;
        }
        uint4* d4 = (uint4*)(bsw + tid * 40);
#pragma unroll
        for (int i = 0; i < 8; ++i) d4[i] = make_uint4(pw[4 * i], pw[4 * i + 1], pw[4 * i + 2], pw[4 * i + 3]);
    }
    __syncthreads();

    // ---------------- A fragments: M=32 (rows ra, ra+8, ra+16, ra+24) ----------------
    const int ra = wid * 32 + rg;
    unsigned a[32];
#pragma unroll
    for (int b = 0; b < 2; ++b)
#pragma unroll
        for (int ks = 0; ks < 4; ++ks) {
            int rbase = (ra + 16 * b) * 36;
            a[b * 16 + ks * 4 + 0] = zbw[rbase + q + ks * 8];
            a[b * 16 + ks * 4 + 1] = zbw[rbase + 8 * 36 + q + ks * 8];
            a[b * 16 + ks * 4 + 2] = zbw[rbase + q + 4 + ks * 8];
            a[b * 16 + ks * 4 + 3] = zbw[rbase + 8 * 36 + q + 4 + ks * 8];
        }
    const float2* ee2p = (const float2*)eef;

    // ---------------- pass 1: fast mins (score = ee - 2 z.e) ----------------
    float mr0 = 1e30f, mr1 = 1e30f, mr2 = 1e30f, mr3 = 1e30f;
#pragma unroll 2
    for (int t = 0; t < NTILES; ++t) {
        float2 e2 = ee2p[t * 4 + q];
        float c0 = e2.x, c1 = e2.y, c2 = e2.x, c3 = e2.y;
        float c4 = e2.x, c5 = e2.y, c6 = e2.x, c7 = e2.y;
        const unsigned* bp = bsw + (t * 8 + rg) * 40 + 2 * q;
#pragma unroll
        for (int ks = 0; ks < 4; ++ks) {
            uint2 b = *(const uint2*)(bp + ks * 8);
            mma16816(c0, c1, c2, c3, a[ks * 4], a[ks * 4 + 1], a[ks * 4 + 2], a[ks * 4 + 3], b.x, b.y);
            mma16816(c4, c5, c6, c7, a[16 + ks * 4], a[17 + ks * 4], a[18 + ks * 4], a[19 + ks * 4], b.x, b.y);
        }
        mr0 = fminf(mr0, fminf(c0, c1));
        mr1 = fminf(mr1, fminf(c2, c3));
        mr2 = fminf(mr2, fminf(c4, c5));
        mr3 = fminf(mr3, fminf(c6, c7));
        float tm = fminf(fminf(fminf(c0, c1), fminf(c2, c3)),
                         fminf(fminf(c4, c5), fminf(c6, c7)));
        tm = fminf(tm, __shfl_xor_sync(0xffffffffu, tm, 1));
        tm = fminf(tm, __shfl_xor_sync(0xffffffffu, tm, 2));
        if (q == 0) tminp[(wid * NTILES + t) * 8 + rg] = __float2half(tm);
    }
    __syncwarp();

#pragma unroll
    for (int off = 1; off < 4; off <<= 1) {
        mr0 = fminf(mr0, __shfl_xor_sync(0xffffffffu, mr0, off));
        mr1 = fminf(mr1, __shfl_xor_sync(0xffffffffu, mr1, off));
        mr2 = fminf(mr2, __shfl_xor_sync(0xffffffffu, mr2, off));
        mr3 = fminf(mr3, __shfl_xor_sync(0xffffffffu, mr3, off));
    }
    const float t0 = mr0 + MARGIN, t1 = mr1 + MARGIN;
    const float t2 = mr2 + MARGIN, t3 = mr3 + MARGIN;
    const float thrq = fmaxf(fmaxf(t0, t1), fmaxf(t2, t3)) + PRUNE_SLACK;

    // ---------------- pass 2: pruned recompute, enqueue candidates ----------------
#define PUSH(rowv, jv) do {                                                       \
        unsigned pk_ = (unsigned)(rowv) | ((unsigned)(jv) << 9);                  \
        int qi_ = atomicAdd(qcnt + wid, 1);                                       \
        if (qi_ < QCAP) que[wid * QCAP + qi_] = pk_;                              \
        else exact_commit(pk_, z, cb, blockRow, zzs, eef, minr);                  \
    } while (0)

#pragma unroll 1
    for (int t = 0; t < NTILES; ++t) {
        float tm = __half2float(tminp[(wid * NTILES + t) * 8 + rg]);
        if (!__any_sync(0xffffffffu, tm <= thrq)) continue;

        float2 e2 = ee2p[t * 4 + q];
        float c0 = e2.x, c1 = e2.y, c2 = e2.x, c3 = e2.y;
        float c4 = e2.x, c5 = e2.y, c6 = e2.x, c7 = e2.y;
        const unsigned* bp = bsw + (t * 8 + rg) * 40 + 2 * q;
#pragma unroll
        for (int ks = 0; ks < 4; ++ks) {
            uint2 b = *(const uint2*)(bp + ks * 8);
            mma16816(c0, c1, c2, c3, a[ks * 4], a[ks * 4 + 1], a[ks * 4 + 2], a[ks * 4 + 3], b.x, b.y);
            mma16816(c4, c5, c6, c7, a[16 + ks * 4], a[17 + ks * 4], a[18 + ks * 4], a[19 + ks * 4], b.x, b.y);
        }
        int jb = t * 8 + 2 * q;
        if (c0 <= t0) PUSH(ra, jb);
        if (c1 <= t0) PUSH(ra, jb + 1);
        if (c2 <= t1) PUSH(ra + 8, jb);
        if (c3 <= t1) PUSH(ra + 8, jb + 1);
        if (c4 <= t2) PUSH(ra + 16, jb);
        if (c5 <= t2) PUSH(ra + 16, jb + 1);
        if (c6 <= t3) PUSH(ra + 24, jb);
        if (c7 <= t3) PUSH(ra + 24, jb + 1);
    }
#undef PUSH

    // ---------------- drain queue: 32 lanes rescore distinct candidates ----------------
    __syncwarp();
    int n = *(volatile int*)(qcnt + wid);
    if (n > QCAP) n = QCAP;
    for (int base = 0; base < n; base += 32) {
        int k2 = base + lane;
        if (k2 < n) exact_commit(que[wid * QCAP + k2], z, cb, blockRow, zzs, eef, minr);
    }
    __syncthreads();

    // ---------------- gather + write both tuple halves ----------------
#pragma unroll
    for (int it = 0; it < 2; ++it) {
        int row = (tid >> 1) + it * 256, hh = tid & 1;
        int j = (int)(unsigned)(minr[row] & 0xFFFFFFFFull);
        size_t g = blockRow + row;
        const float4* s4 = (const float4*)(cb + (size_t)j * Dm + hh * 32);
        float4* o1 = (float4*)(out + g * Dm + hh * 32);
        float4* o2 = (half > 0) ? (float4*)(out + half + g * Dm + hh * 32) : nullptr;
#pragma unroll
        for (int i = 0; i < 8; ++i) {
            float4 tv = s4[i];
            o1[i] = tv;
            if (o2) o2[i] = tv;
        }
    }
}

extern "C" void kernel_launch(void* const* d_in, const int* in_sizes, int n_in,
                              void* d_out, int out_size) {
    const float* z = (const float*)d_in[0];
    const float* cb = (const float*)d_in[1];
    float* out = (float*)d_out;
    const int N = in_sizes[0] / Dm;                      // 131072
    long long half = ((long long)out_size >= 2LL * N * Dm) ? (long long)out_size / 2 : 0;

    cudaFuncSetAttribute(vq_kernel, cudaFuncAttributeMaxDynamicSharedMemorySize, SM_TOTAL);
    vq_kernel<<<N / ROWS_CTA, THREADS, SM_TOTAL>>>(z, cb, out, half);
}